// round 6
// baseline (speedup 1.0000x reference)
#include <cuda_runtime.h>
#include <cuda_bf16.h>
#include <cstdint>
#include <math.h>

typedef unsigned int u32;
typedef unsigned long long u64;

#define HID 512
#define ALPHA 0.01f
#define N_INT_MAX 20000
#define N_BND_MAX 800
#define MT_MAX 656
#define NB_RED 64
#define RED_T 256
#define SMEM_LAYER 69632   // 4096 header + 2 * 32768 stages

// A operand (jets), bf16 hi/lo, [stage][mtile][128 rows][512 k]
__device__ __nv_bfloat16 gAh[2][(size_t)MT_MAX * 128 * 512];
__device__ __nv_bfloat16 gAl[2][(size_t)MT_MAX * 128 * 512];
// B operand (W^T), bf16 hi/lo, [layer][512 n][512 k]
__device__ __nv_bfloat16 gBh[2][512 * 512];
__device__ __nv_bfloat16 gBl[2][512 * 512];
// per-nquad partials
__device__ float g_lp[4][N_INT_MAX];
__device__ float g_up[4][N_BND_MAX];
__device__ double g_part[2 * NB_RED];

// ---------------- helpers ----------------
__device__ __forceinline__ void cp16(u32 dst, const void* src) {
    asm volatile("cp.async.cg.shared.global [%0], [%1], 16;" :: "r"(dst), "l"(src));
}
__device__ __forceinline__ void cp_commit() { asm volatile("cp.async.commit_group;"); }
__device__ __forceinline__ void cp_wait1()  { asm volatile("cp.async.wait_group 1;"); }
__device__ __forceinline__ void cp_wait0()  { asm volatile("cp.async.wait_group 0;"); }

__device__ __forceinline__ void ldsm4(u32& r0, u32& r1, u32& r2, u32& r3, u32 addr) {
    asm volatile("ldmatrix.sync.aligned.m8n8.x4.shared.b16 {%0,%1,%2,%3}, [%4];"
        : "=r"(r0), "=r"(r1), "=r"(r2), "=r"(r3) : "r"(addr));
}
__device__ __forceinline__ void mma_bf16(float* c, const u32* a, u32 b0, u32 b1) {
    asm volatile("mma.sync.aligned.m16n8k16.row.col.f32.bf16.bf16.f32 "
        "{%0,%1,%2,%3}, {%4,%5,%6,%7}, {%8,%9}, {%0,%1,%2,%3};"
        : "+f"(c[0]), "+f"(c[1]), "+f"(c[2]), "+f"(c[3])
        : "r"(a[0]), "r"(a[1]), "r"(a[2]), "r"(a[3]), "r"(b0), "r"(b1));
}
__device__ __forceinline__ void split_bf16(float v, __nv_bfloat16& hi, __nv_bfloat16& lo) {
    hi = __float2bfloat16_rn(v);
    lo = __float2bfloat16_rn(v - __bfloat162float(hi));
}
__device__ __forceinline__ u32 pack_bf2(__nv_bfloat16 a, __nv_bfloat16 b) {
    return (u32)__bfloat16_as_ushort(a) | ((u32)__bfloat16_as_ushort(b) << 16);
}

// ---------------- fused prep: W transpose-split (512 blocks) + layer-0 jets (650+) ----------------
__global__ void __launch_bounds__(256) prep_all(
    const float* __restrict__ xi, const float* __restrict__ xb,
    const float* __restrict__ W0, const float* __restrict__ b0,
    const float* __restrict__ W1, const float* __restrict__ W2,
    int n_int, int n_bnd)
{
    __shared__ float sm[32][33];
    __shared__ float s_wx[512], s_wy[512], s_b[512], s_x[32], s_y[32];
    const int tid = threadIdx.x;

    if (blockIdx.x < 512) {
        // ---- transpose W (k-major) -> gB (n-major), bf16 hi/lo split ----
        int b = blockIdx.x;
        int l = b >> 8, rem = b & 255;
        int kt = rem & 15, nt = rem >> 4;
        const float* W = l ? W2 : W1;
        int tx = tid & 31, ty = tid >> 5;
        #pragma unroll
        for (int i = 0; i < 4; i++)
            sm[ty + 8 * i][tx] = W[(size_t)(kt * 32 + ty + 8 * i) * 512 + nt * 32 + tx];
        __syncthreads();
        #pragma unroll
        for (int i = 0; i < 4; i++) {
            int n = nt * 32 + ty + 8 * i;
            int k = kt * 32 + tx;
            float v = sm[tx][ty + 8 * i];
            __nv_bfloat16 hi, lo; split_bf16(v, hi, lo);
            gBh[l][(size_t)n * 512 + k] = hi;
            gBl[l][(size_t)n * 512 + k] = lo;
        }
        return;
    }

    // ---- layer-0 jets -> A0 ----
    const int mt = blockIdx.x - 512;
    for (int i = tid; i < 512; i += 256) {
        s_wx[i] = W0[i]; s_wy[i] = W0[512 + i]; s_b[i] = b0[i];
    }
    if (tid < 32) {
        int gp = mt * 32 + tid;
        float x = 0.f, y = 0.f;
        if (gp < n_int) { x = xi[2 * gp]; y = xi[2 * gp + 1]; }
        else if (gp < n_int + n_bnd) { x = xb[2 * (gp - n_int)]; y = xb[2 * (gp - n_int) + 1]; }
        s_x[tid] = x; s_y[tid] = y;
    }
    __syncthreads();
    u32* Oh = (u32*)(gAh[0] + (size_t)mt * 65536);
    u32* Ol = (u32*)(gAl[0] + (size_t)mt * 65536);
    for (int it = tid; it < 32 * 256; it += 256) {
        int p = it >> 8, n2 = it & 255;
        float cj[2][4];
        #pragma unroll
        for (int e = 0; e < 2; e++) {
            int n = 2 * n2 + e;
            float wx = s_wx[n], wy = s_wy[n];
            float z = fmaf(s_x[p], wx, fmaf(s_y[p], wy, s_b[n]));
            float tt = tanhf(z), sd = 1.f - tt * tt;
            cj[e][0] = tt; cj[e][1] = sd * wx; cj[e][2] = sd * wy;
            cj[e][3] = -2.f * tt * sd * (wx * wx + wy * wy);
        }
        #pragma unroll
        for (int cc = 0; cc < 4; cc++) {
            __nv_bfloat16 h0, l0, h1, l1;
            split_bf16(cj[0][cc], h0, l0);
            split_bf16(cj[1][cc], h1, l1);
            u32 off = (u32)(4 * p + cc) * 256 + n2;
            Oh[off] = pack_bf2(h0, h1);
            Ol[off] = pack_bf2(l0, l1);
        }
    }
}

// ---------------- main GEMM layer (mma.sync bf16, 3-product split) ----------------
// grid (mtiles, 4): blockIdx.y = N-quad (128 cols). 256 threads = 8 warps (4M x 2N).
// smem floats: [0..128) bias slice, [128..256) W3 slice, [256..384) reduce, tiles @1024.
// stage (32KB): Ah 8K | Al 8K | Bh 8K | Bl 8K ; unit (row,ch16B) at ch*2048 + row*16.
template<int FINAL>
__global__ void __launch_bounds__(256, 2) layer_k(
    int sIn, const float* __restrict__ bias, const float* __restrict__ W3,
    int n_int, int n_bnd)
{
    extern __shared__ float smem[];
    u32 sb = (u32)__cvta_generic_to_shared(smem);
    const int tid = threadIdx.x, lane = tid & 31, w = tid >> 5;
    const int warpM = w & 3, warpN = w >> 2;
    const int mt = blockIdx.x, nq = blockIdx.y;

    float* s_bias = smem;
    float* s_w3   = smem + 128;
    float* s_red  = smem + 256;

    if (tid < 128) {
        s_bias[tid] = bias[nq * 128 + tid];
        if (FINAL) s_w3[tid] = W3[nq * 128 + tid];
    }

    const char* Ah = (const char*)(gAh[sIn] + (size_t)mt * 65536);
    const char* Al = (const char*)(gAl[sIn] + (size_t)mt * 65536);
    const char* Bh = (const char*)(gBh[sIn] + (size_t)nq * 128 * 512);
    const char* Bl = (const char*)(gBl[sIn] + (size_t)nq * 128 * 512);

    auto fill = [&](int kt) {
        u32 base = sb + 4096u + (u32)(kt & 1) * 32768u;
        #pragma unroll
        for (int i = 0; i < 2; i++) {
            int u = tid + i * 256;
            int ch = u & 3, row = u >> 2;
            u32 d = base + (u32)ch * 2048u + (u32)row * 16u;
            size_t s = (size_t)row * 1024 + kt * 64 + ch * 16;
            cp16(d,           Ah + s);
            cp16(d + 8192u,   Al + s);
            cp16(d + 16384u,  Bh + s);
            cp16(d + 24576u,  Bl + s);
        }
    };

    float acc[2][8][4];
    #pragma unroll
    for (int mi = 0; mi < 2; mi++)
        #pragma unroll
        for (int ni = 0; ni < 8; ni++)
            #pragma unroll
            for (int r = 0; r < 4; r++) acc[mi][ni][r] = 0.f;

    fill(0); cp_commit();
    fill(1); cp_commit();

    const int rowA = (lane & 7) + (lane & 8);          // + warpM*32 + mi*16
    const int chAh = (lane >> 4) & 1;
    const int rowB = (lane & 7) + ((lane & 16) >> 1);  // + warpN*64 + ni2*16
    const int chBh = (lane >> 3) & 1;

    #pragma unroll 1
    for (int kt = 0; kt < 16; kt++) {
        if (kt >= 14) cp_wait0(); else cp_wait1();
        __syncthreads();
        u32 tb = sb + 4096u + (u32)(kt & 1) * 32768u;
        #pragma unroll
        for (int ks = 0; ks < 2; ks++) {
            u32 ah[2][4], al[2][4];
            #pragma unroll
            for (int mi = 0; mi < 2; mi++) {
                int row = warpM * 32 + mi * 16 + rowA;
                u32 ad = tb + (u32)(ks * 2 + chAh) * 2048u + (u32)row * 16u;
                ldsm4(ah[mi][0], ah[mi][1], ah[mi][2], ah[mi][3], ad);
                ldsm4(al[mi][0], al[mi][1], al[mi][2], al[mi][3], ad + 8192u);
            }
            #pragma unroll
            for (int ni2 = 0; ni2 < 4; ni2++) {
                int row = warpN * 64 + ni2 * 16 + rowB;
                u32 bd = tb + 16384u + (u32)(ks * 2 + chBh) * 2048u + (u32)row * 16u;
                u32 bh[4], bl[4];
                ldsm4(bh[0], bh[1], bh[2], bh[3], bd);
                ldsm4(bl[0], bl[1], bl[2], bl[3], bd + 8192u);
                #pragma unroll
                for (int mi = 0; mi < 2; mi++) {
                    float* c0 = acc[mi][ni2 * 2];
                    float* c1 = acc[mi][ni2 * 2 + 1];
                    mma_bf16(c0, ah[mi], bh[0], bh[1]);
                    mma_bf16(c0, al[mi], bh[0], bh[1]);
                    mma_bf16(c0, ah[mi], bl[0], bl[1]);
                    mma_bf16(c1, ah[mi], bh[2], bh[3]);
                    mma_bf16(c1, al[mi], bh[2], bh[3]);
                    mma_bf16(c1, ah[mi], bl[2], bl[3]);
                }
            }
        }
        __syncthreads();
        if (kt + 2 < 16) { fill(kt + 2); cp_commit(); }
    }

    // ---------------- epilogue ----------------
    const int t4 = lane & 3;
    const int gg = lane >> 2;
    const int cmy = gg & 3;
    const int baseLane = lane & 0x13;
    float du[4] = {0.f, 0.f, 0.f, 0.f};
    float dl[4] = {0.f, 0.f, 0.f, 0.f};
    u32* Oh = (u32*)(gAh[sIn ^ 1] + (size_t)mt * 65536);
    u32* Ol = (u32*)(gAl[sIn ^ 1] + (size_t)mt * 65536);

    #pragma unroll
    for (int mi = 0; mi < 2; mi++) {
        #pragma unroll
        for (int rh = 0; rh < 2; rh++) {
            int R = warpM * 32 + mi * 16 + rh * 8 + gg;
            #pragma unroll
            for (int ni = 0; ni < 8; ni++) {
                float vv[2];
                #pragma unroll
                for (int ch = 0; ch < 2; ch++) {
                    float z = acc[mi][ni][rh * 2 + ch];
                    float zv  = __shfl_sync(0xffffffffu, z, baseLane);
                    float zgx = __shfl_sync(0xffffffffu, z, baseLane | 4);
                    float zgy = __shfl_sync(0xffffffffu, z, baseLane | 8);
                    float zL  = __shfl_sync(0xffffffffu, z, baseLane | 12);
                    int n_loc = warpN * 64 + ni * 8 + 2 * t4 + ch;
                    float tt = tanhf(zv + s_bias[n_loc]);
                    float sd = 1.f - tt * tt;
                    float Lo = fmaf(sd, zL, -2.f * tt * sd * (zgx * zgx + zgy * zgy));
                    if (FINAL) {
                        float w3 = s_w3[n_loc];
                        du[mi * 2 + rh] = fmaf(tt, w3, du[mi * 2 + rh]);
                        dl[mi * 2 + rh] = fmaf(Lo, w3, dl[mi * 2 + rh]);
                    } else {
                        vv[ch] = (cmy == 0) ? tt : (cmy == 1) ? sd * zgx
                               : (cmy == 2) ? sd * zgy : Lo;
                    }
                }
                if (!FINAL) {
                    __nv_bfloat16 h0, l0, h1, l1;
                    split_bf16(vv[0], h0, l0);
                    split_bf16(vv[1], h1, l1);
                    u32 eo = (u32)R * 256 + (u32)(nq * 128 + warpN * 64 + ni * 8 + 2 * t4) / 2;
                    Oh[eo] = pack_bf2(h0, h1);
                    Ol[eo] = pack_bf2(l0, l1);
                }
            }
        }
    }

    if (FINAL) {
        #pragma unroll
        for (int s = 0; s < 4; s++) {
            du[s] += __shfl_xor_sync(0xffffffffu, du[s], 1);
            du[s] += __shfl_xor_sync(0xffffffffu, du[s], 2);
            dl[s] += __shfl_xor_sync(0xffffffffu, dl[s], 1);
            dl[s] += __shfl_xor_sync(0xffffffffu, dl[s], 2);
        }
        float* s_u = s_red;
        float* s_l = s_red + 64;
        if (lane == 0 || lane == 16) {
            int ghi = lane >> 4;
            #pragma unroll
            for (int mi = 0; mi < 2; mi++)
                #pragma unroll
                for (int rh = 0; rh < 2; rh++) {
                    int p = warpM * 8 + mi * 4 + rh * 2 + ghi;
                    s_u[warpN * 32 + p] = du[mi * 2 + rh];
                    s_l[warpN * 32 + p] = dl[mi * 2 + rh];
                }
        }
        __syncthreads();
        if (tid < 32) {
            int pt = mt * 32 + tid;
            float us = s_u[tid] + s_u[32 + tid];
            float ls = s_l[tid] + s_l[32 + tid];
            if (pt < n_int) g_lp[nq][pt] = ls;
            else if (pt < n_int + n_bnd) g_up[nq][pt - n_int] = us;
        }
    }
}

// ---------------- two-stage deterministic reduction ----------------
__global__ void pinn_partial(const float* __restrict__ xi, const float* __restrict__ b3,
                             int n_int, int n_bnd)
{
    __shared__ double sh[2 * RED_T];
    const int tid = threadIdx.x;
    const int stride = NB_RED * RED_T;
    const float PI = 3.14159265358979f;
    float b3v = b3[0];

    double si = 0.0, sb = 0.0;
    for (int i = blockIdx.x * RED_T + tid; i < n_int; i += stride) {
        float xx = xi[2 * i], yy = xi[2 * i + 1];
        float y2 = yy * yy;
        float sp = sinf(PI * xx);
        float s2, c2; sincosf(PI * y2, &s2, &c2);
        float f = -PI * PI * (1.0f + 4.0f * y2) * sp * s2 + 2.0f * PI * sp * c2;
        float r = (g_lp[0][i] + g_lp[1][i] + g_lp[2][i] + g_lp[3][i]) - f;
        si += (double)r * r;
    }
    for (int i = blockIdx.x * RED_T + tid; i < n_bnd; i += stride) {
        float u = g_up[0][i] + g_up[1][i] + g_up[2][i] + g_up[3][i] + b3v;
        sb += (double)u * u;
    }
    sh[tid] = si; sh[RED_T + tid] = sb;
    __syncthreads();
    for (int s = RED_T / 2; s > 0; s >>= 1) {
        if (tid < s) { sh[tid] += sh[tid + s]; sh[RED_T + tid] += sh[RED_T + tid + s]; }
        __syncthreads();
    }
    if (tid == 0) {
        g_part[blockIdx.x] = sh[0];
        g_part[NB_RED + blockIdx.x] = sh[RED_T];
    }
}

__global__ void pinn_final(float* __restrict__ out, int n_int, int n_bnd)
{
    __shared__ double sh[2 * NB_RED];
    int tid = threadIdx.x;
    if (tid < 2 * NB_RED) sh[tid] = g_part[tid];
    __syncthreads();
    if (tid == 0) {
        double si = 0.0, sb = 0.0;
        for (int i = 0; i < NB_RED; i++) { si += sh[i]; sb += sh[NB_RED + i]; }
        double il = si / (double)n_int;
        double bl = sb / (double)n_bnd;
        out[0] = (float)((double)ALPHA * il + bl);
        out[1] = (float)il;
        out[2] = (float)bl;
    }
}

extern "C" void kernel_launch(void* const* d_in, const int* in_sizes, int n_in,
                              void* d_out, int out_size)
{
    const float* xi = (const float*)d_in[0];
    const float* xb = (const float*)d_in[1];
    const float* W0 = (const float*)d_in[2];
    const float* b0 = (const float*)d_in[3];
    const float* W1 = (const float*)d_in[4];
    const float* b1 = (const float*)d_in[5];
    const float* W2 = (const float*)d_in[6];
    const float* b2 = (const float*)d_in[7];
    const float* W3 = (const float*)d_in[8];
    const float* b3 = (const float*)d_in[9];

    int n_int = in_sizes[0] / 2;
    int n_bnd = in_sizes[1] / 2;
    int n_total = n_int + n_bnd;
    int mtiles = (n_total + 31) / 32;

    static int configured = 0;
    if (!configured) {
        cudaFuncSetAttribute(layer_k<0>, cudaFuncAttributeMaxDynamicSharedMemorySize, SMEM_LAYER);
        cudaFuncSetAttribute(layer_k<1>, cudaFuncAttributeMaxDynamicSharedMemorySize, SMEM_LAYER);
        configured = 1;
    }

    prep_all<<<512 + mtiles, 256>>>(xi, xb, W0, b0, W1, W2, n_int, n_bnd);
    dim3 grid(mtiles, 4);
    layer_k<0><<<grid, 256, SMEM_LAYER>>>(0, b1, W3, n_int, n_bnd);
    layer_k<1><<<grid, 256, SMEM_LAYER>>>(1, b2, W3, n_int, n_bnd);
    pinn_partial<<<NB_RED, RED_T>>>(xi, b3, n_int, n_bnd);
    pinn_final<<<1, 128>>>((float*)d_out, n_int, n_bnd);
}

// round 8
// speedup vs baseline: 1.4671x; 1.4671x over previous
#include <cuda_runtime.h>
#include <cuda_bf16.h>
#include <cstdint>
#include <math.h>

typedef unsigned int u32;
typedef unsigned long long u64;

#define HID 512
#define ALPHA 0.01f
#define N_INT_MAX 20000
#define N_BND_MAX 800
#define MT_MAX 656
#define NB_RED 64
#define RED_T 256
// header 4096 + 4 stages * 49152
#define STAGE_BYTES 49152
#define SMEM_LAYER (4096 + 4 * STAGE_BYTES)

// A operand (jets), bf16 hi/lo, [stage][mtile][128 rows][512 k]
__device__ __nv_bfloat16 gAh[2][(size_t)MT_MAX * 128 * 512];
__device__ __nv_bfloat16 gAl[2][(size_t)MT_MAX * 128 * 512];
// B operand (W^T), bf16 hi/lo, [layer][512 n][512 k]
__device__ __nv_bfloat16 gBh[2][512 * 512];
__device__ __nv_bfloat16 gBl[2][512 * 512];
// per-nhalf partials
__device__ float g_lp[2][N_INT_MAX];
__device__ float g_up[2][N_BND_MAX];
__device__ double g_part[2 * NB_RED];

// ---------------- helpers ----------------
__device__ __forceinline__ void cp16(u32 dst, const void* src) {
    asm volatile("cp.async.cg.shared.global [%0], [%1], 16;" :: "r"(dst), "l"(src));
}
__device__ __forceinline__ void cp_commit() { asm volatile("cp.async.commit_group;"); }
__device__ __forceinline__ void cp_wait2()  { asm volatile("cp.async.wait_group 2;"); }
__device__ __forceinline__ void cp_wait1()  { asm volatile("cp.async.wait_group 1;"); }
__device__ __forceinline__ void cp_wait0()  { asm volatile("cp.async.wait_group 0;"); }

__device__ __forceinline__ void ldsm4(u32& r0, u32& r1, u32& r2, u32& r3, u32 addr) {
    asm volatile("ldmatrix.sync.aligned.m8n8.x4.shared.b16 {%0,%1,%2,%3}, [%4];"
        : "=r"(r0), "=r"(r1), "=r"(r2), "=r"(r3) : "r"(addr));
}
__device__ __forceinline__ void mma_bf16(float* c, const u32* a, u32 b0, u32 b1) {
    asm volatile("mma.sync.aligned.m16n8k16.row.col.f32.bf16.bf16.f32 "
        "{%0,%1,%2,%3}, {%4,%5,%6,%7}, {%8,%9}, {%0,%1,%2,%3};"
        : "+f"(c[0]), "+f"(c[1]), "+f"(c[2]), "+f"(c[3])
        : "r"(a[0]), "r"(a[1]), "r"(a[2]), "r"(a[3]), "r"(b0), "r"(b1));
}
__device__ __forceinline__ void split_bf16(float v, __nv_bfloat16& hi, __nv_bfloat16& lo) {
    hi = __float2bfloat16_rn(v);
    lo = __float2bfloat16_rn(v - __bfloat162float(hi));
}
__device__ __forceinline__ u32 pack_bf2(__nv_bfloat16 a, __nv_bfloat16 b) {
    return (u32)__bfloat16_as_ushort(a) | ((u32)__bfloat16_as_ushort(b) << 16);
}

// ---------------- fused prep: W transpose-split (512 blocks) + layer-0 jets ----------------
__global__ void __launch_bounds__(256) prep_all(
    const float* __restrict__ xi, const float* __restrict__ xb,
    const float* __restrict__ W0, const float* __restrict__ b0,
    const float* __restrict__ W1, const float* __restrict__ W2,
    int n_int, int n_bnd)
{
    __shared__ float sm[32][33];
    __shared__ float s_wx[512], s_wy[512], s_b[512], s_x[32], s_y[32];
    const int tid = threadIdx.x;

    if (blockIdx.x < 512) {
        // ---- transpose W (k-major) -> gB (n-major), bf16 hi/lo split ----
        int b = blockIdx.x;
        int l = b >> 8, rem = b & 255;
        int kt = rem & 15, nt = rem >> 4;
        const float* W = l ? W2 : W1;
        int tx = tid & 31, ty = tid >> 5;
        #pragma unroll
        for (int i = 0; i < 4; i++)
            sm[ty + 8 * i][tx] = W[(size_t)(kt * 32 + ty + 8 * i) * 512 + nt * 32 + tx];
        __syncthreads();
        #pragma unroll
        for (int i = 0; i < 4; i++) {
            int n = nt * 32 + ty + 8 * i;
            int k = kt * 32 + tx;
            float v = sm[tx][ty + 8 * i];
            __nv_bfloat16 hi, lo; split_bf16(v, hi, lo);
            gBh[l][(size_t)n * 512 + k] = hi;
            gBl[l][(size_t)n * 512 + k] = lo;
        }
        return;
    }

    // ---- layer-0 jets -> A0 ----
    const int mt = blockIdx.x - 512;
    for (int i = tid; i < 512; i += 256) {
        s_wx[i] = W0[i]; s_wy[i] = W0[512 + i]; s_b[i] = b0[i];
    }
    if (tid < 32) {
        int gp = mt * 32 + tid;
        float x = 0.f, y = 0.f;
        if (gp < n_int) { x = xi[2 * gp]; y = xi[2 * gp + 1]; }
        else if (gp < n_int + n_bnd) { x = xb[2 * (gp - n_int)]; y = xb[2 * (gp - n_int) + 1]; }
        s_x[tid] = x; s_y[tid] = y;
    }
    __syncthreads();
    u32* Oh = (u32*)(gAh[0] + (size_t)mt * 65536);
    u32* Ol = (u32*)(gAl[0] + (size_t)mt * 65536);
    for (int it = tid; it < 32 * 256; it += 256) {
        int p = it >> 8, n2 = it & 255;
        float cj[2][4];
        #pragma unroll
        for (int e = 0; e < 2; e++) {
            int n = 2 * n2 + e;
            float wx = s_wx[n], wy = s_wy[n];
            float z = fmaf(s_x[p], wx, fmaf(s_y[p], wy, s_b[n]));
            float tt = tanhf(z), sd = 1.f - tt * tt;
            cj[e][0] = tt; cj[e][1] = sd * wx; cj[e][2] = sd * wy;
            cj[e][3] = -2.f * tt * sd * (wx * wx + wy * wy);
        }
        #pragma unroll
        for (int cc = 0; cc < 4; cc++) {
            __nv_bfloat16 h0, l0, h1, l1;
            split_bf16(cj[0][cc], h0, l0);
            split_bf16(cj[1][cc], h1, l1);
            u32 off = (u32)(4 * p + cc) * 256 + n2;
            Oh[off] = pack_bf2(h0, h1);
            Ol[off] = pack_bf2(l0, l1);
        }
    }
}

// ---------------- main GEMM layer (mma.sync bf16, 3-product split) ----------------
// grid (mtiles, 2): blockIdx.y = N-half (256 cols). 256 threads = 8 warps (4M x 2N).
// 4-stage ring, K-chunk 32. Stage layout (48KB):
//   Ah: ch*2048 + row*16   (128 rows x 4 ch, 8KB)   @ +0
//   Al: same               @ +8192
//   Bh: ch*4096 + row*16   (256 rows x 4 ch, 16KB)  @ +16384
//   Bl: same               @ +32768
template<int FINAL>
__global__ void __launch_bounds__(256, 1) layer_k(
    int sIn, const float* __restrict__ bias, const float* __restrict__ W3,
    int n_int, int n_bnd)
{
    extern __shared__ float smem[];
    u32 sb = (u32)__cvta_generic_to_shared(smem);
    const int tid = threadIdx.x, lane = tid & 31, w = tid >> 5;
    const int warpM = w & 3, warpN = w >> 2;
    const int mt = blockIdx.x, nhalf = blockIdx.y;

    float* s_bias = smem;          // 256
    float* s_w3   = smem + 256;    // 256
    float* s_red  = smem + 512;    // 128

    if (tid < 256) {
        s_bias[tid] = bias[nhalf * 256 + tid];
        if (FINAL) s_w3[tid] = W3[nhalf * 256 + tid];
    }

    const char* Ah = (const char*)(gAh[sIn] + (size_t)mt * 65536);
    const char* Al = (const char*)(gAl[sIn] + (size_t)mt * 65536);
    const char* Bh = (const char*)(gBh[sIn] + (size_t)nhalf * 256 * 512);
    const char* Bl = (const char*)(gBl[sIn] + (size_t)nhalf * 256 * 512);

    auto fill = [&](int kt) {
        u32 base = sb + 4096u + (u32)(kt & 3) * (u32)STAGE_BYTES;
        // A: 128 rows x 4 chunks, hi+lo
        #pragma unroll
        for (int i = 0; i < 2; i++) {
            int u = tid + i * 256;
            int ch = u & 3, row = u >> 2;
            u32 d = base + (u32)ch * 2048u + (u32)row * 16u;
            size_t s = (size_t)row * 1024 + (size_t)kt * 64 + (size_t)ch * 16;
            cp16(d,          Ah + s);
            cp16(d + 8192u,  Al + s);
        }
        // B: 256 rows x 4 chunks, hi+lo
        #pragma unroll
        for (int i = 0; i < 4; i++) {
            int u = tid + i * 256;
            int ch = u & 3, row = u >> 2;
            u32 d = base + 16384u + (u32)ch * 4096u + (u32)row * 16u;
            size_t s = (size_t)row * 1024 + (size_t)kt * 64 + (size_t)ch * 16;
            cp16(d,           Bh + s);
            cp16(d + 16384u,  Bl + s);
        }
    };

    float acc[2][16][4];
    #pragma unroll
    for (int mi = 0; mi < 2; mi++)
        #pragma unroll
        for (int ni = 0; ni < 16; ni++)
            #pragma unroll
            for (int r = 0; r < 4; r++) acc[mi][ni][r] = 0.f;

    fill(0); cp_commit();
    fill(1); cp_commit();
    fill(2); cp_commit();

    const int rowA = (lane & 7) + (lane & 8);          // + warpM*32 + mi*16
    const int chAh = (lane >> 4) & 1;
    const int rowB = (lane & 7) + ((lane & 16) >> 1);  // + warpN*128 + ni2*16
    const int chBh = (lane >> 3) & 1;

    #pragma unroll 1
    for (int kt = 0; kt < 16; kt++) {
        if (kt <= 13) cp_wait2();
        else if (kt == 14) cp_wait1();
        else cp_wait0();
        __syncthreads();
        // prefetch stage kt+3 (writes buffer (kt-1)&3, all MMAs on it are done)
        if (kt + 3 < 16) { fill(kt + 3); cp_commit(); }

        u32 tb = sb + 4096u + (u32)(kt & 3) * (u32)STAGE_BYTES;
        #pragma unroll
        for (int ks = 0; ks < 2; ks++) {
            u32 ah[2][4], al[2][4];
            #pragma unroll
            for (int mi = 0; mi < 2; mi++) {
                int row = warpM * 32 + mi * 16 + rowA;
                u32 ad = tb + (u32)(ks * 2 + chAh) * 2048u + (u32)row * 16u;
                ldsm4(ah[mi][0], ah[mi][1], ah[mi][2], ah[mi][3], ad);
                ldsm4(al[mi][0], al[mi][1], al[mi][2], al[mi][3], ad + 8192u);
            }
            #pragma unroll
            for (int ni2 = 0; ni2 < 8; ni2++) {
                int row = warpN * 128 + ni2 * 16 + rowB;
                u32 bd = tb + 16384u + (u32)(ks * 2 + chBh) * 4096u + (u32)row * 16u;
                u32 bh[4], bl[4];
                ldsm4(bh[0], bh[1], bh[2], bh[3], bd);
                ldsm4(bl[0], bl[1], bl[2], bl[3], bd + 16384u);
                #pragma unroll
                for (int mi = 0; mi < 2; mi++) {
                    float* c0 = acc[mi][ni2 * 2];
                    float* c1 = acc[mi][ni2 * 2 + 1];
                    mma_bf16(c0, ah[mi], bh[0], bh[1]);
                    mma_bf16(c0, al[mi], bh[0], bh[1]);
                    mma_bf16(c0, ah[mi], bl[0], bl[1]);
                    mma_bf16(c1, ah[mi], bh[2], bh[3]);
                    mma_bf16(c1, al[mi], bh[2], bh[3]);
                    mma_bf16(c1, ah[mi], bl[2], bl[3]);
                }
            }
        }
    }

    // ---------------- epilogue ----------------
    const int t4 = lane & 3;
    const int gg = lane >> 2;
    const int cmy = gg & 3;
    const int baseLane = lane & 0x13;
    float du[4] = {0.f, 0.f, 0.f, 0.f};
    float dl[4] = {0.f, 0.f, 0.f, 0.f};
    u32* Oh = (u32*)(gAh[sIn ^ 1] + (size_t)mt * 65536);
    u32* Ol = (u32*)(gAl[sIn ^ 1] + (size_t)mt * 65536);

    #pragma unroll
    for (int mi = 0; mi < 2; mi++) {
        #pragma unroll
        for (int rh = 0; rh < 2; rh++) {
            int R = warpM * 32 + mi * 16 + rh * 8 + gg;
            #pragma unroll
            for (int ni = 0; ni < 16; ni++) {
                float vv[2];
                #pragma unroll
                for (int ch = 0; ch < 2; ch++) {
                    float z = acc[mi][ni][rh * 2 + ch];
                    float zv  = __shfl_sync(0xffffffffu, z, baseLane);
                    float zgx = __shfl_sync(0xffffffffu, z, baseLane | 4);
                    float zgy = __shfl_sync(0xffffffffu, z, baseLane | 8);
                    float zL  = __shfl_sync(0xffffffffu, z, baseLane | 12);
                    int n_loc = warpN * 128 + ni * 8 + 2 * t4 + ch;
                    float tt = tanhf(zv + s_bias[n_loc]);
                    float sd = 1.f - tt * tt;
                    float Lo = fmaf(sd, zL, -2.f * tt * sd * (zgx * zgx + zgy * zgy));
                    if (FINAL) {
                        float w3 = s_w3[n_loc];
                        du[mi * 2 + rh] = fmaf(tt, w3, du[mi * 2 + rh]);
                        dl[mi * 2 + rh] = fmaf(Lo, w3, dl[mi * 2 + rh]);
                    } else {
                        vv[ch] = (cmy == 0) ? tt : (cmy == 1) ? sd * zgx
                               : (cmy == 2) ? sd * zgy : Lo;
                    }
                }
                if (!FINAL) {
                    __nv_bfloat16 h0, l0, h1, l1;
                    split_bf16(vv[0], h0, l0);
                    split_bf16(vv[1], h1, l1);
                    u32 eo = (u32)R * 256 + (u32)(nhalf * 256 + warpN * 128 + ni * 8 + 2 * t4) / 2;
                    Oh[eo] = pack_bf2(h0, h1);
                    Ol[eo] = pack_bf2(l0, l1);
                }
            }
        }
    }

    if (FINAL) {
        #pragma unroll
        for (int s = 0; s < 4; s++) {
            du[s] += __shfl_xor_sync(0xffffffffu, du[s], 1);
            du[s] += __shfl_xor_sync(0xffffffffu, du[s], 2);
            dl[s] += __shfl_xor_sync(0xffffffffu, dl[s], 1);
            dl[s] += __shfl_xor_sync(0xffffffffu, dl[s], 2);
        }
        float* s_u = s_red;
        float* s_l = s_red + 64;
        if (lane == 0 || lane == 16) {
            int ghi = lane >> 4;
            #pragma unroll
            for (int mi = 0; mi < 2; mi++)
                #pragma unroll
                for (int rh = 0; rh < 2; rh++) {
                    int p = warpM * 8 + mi * 4 + rh * 2 + ghi;
                    s_u[warpN * 32 + p] = du[mi * 2 + rh];
                    s_l[warpN * 32 + p] = dl[mi * 2 + rh];
                }
        }
        __syncthreads();
        if (tid < 32) {
            int pt = mt * 32 + tid;
            float us = s_u[tid] + s_u[32 + tid];
            float ls = s_l[tid] + s_l[32 + tid];
            if (pt < n_int) g_lp[nhalf][pt] = ls;
            else if (pt < n_int + n_bnd) g_up[nhalf][pt - n_int] = us;
        }
    }
}

// ---------------- two-stage deterministic reduction ----------------
__global__ void pinn_partial(const float* __restrict__ xi, const float* __restrict__ b3,
                             int n_int, int n_bnd)
{
    __shared__ double sh[2 * RED_T];
    const int tid = threadIdx.x;
    const int stride = NB_RED * RED_T;
    const float PI = 3.14159265358979f;
    float b3v = b3[0];

    double si = 0.0, sb = 0.0;
    for (int i = blockIdx.x * RED_T + tid; i < n_int; i += stride) {
        float xx = xi[2 * i], yy = xi[2 * i + 1];
        float y2 = yy * yy;
        float sp = sinf(PI * xx);
        float s2, c2; sincosf(PI * y2, &s2, &c2);
        float f = -PI * PI * (1.0f + 4.0f * y2) * sp * s2 + 2.0f * PI * sp * c2;
        float r = (g_lp[0][i] + g_lp[1][i]) - f;
        si += (double)r * r;
    }
    for (int i = blockIdx.x * RED_T + tid; i < n_bnd; i += stride) {
        float u = g_up[0][i] + g_up[1][i] + b3v;
        sb += (double)u * u;
    }
    sh[tid] = si; sh[RED_T + tid] = sb;
    __syncthreads();
    for (int s = RED_T / 2; s > 0; s >>= 1) {
        if (tid < s) { sh[tid] += sh[tid + s]; sh[RED_T + tid] += sh[RED_T + tid + s]; }
        __syncthreads();
    }
    if (tid == 0) {
        g_part[blockIdx.x] = sh[0];
        g_part[NB_RED + blockIdx.x] = sh[RED_T];
    }
}

__global__ void pinn_final(float* __restrict__ out, int n_int, int n_bnd)
{
    __shared__ double sh[2 * NB_RED];
    int tid = threadIdx.x;
    if (tid < 2 * NB_RED) sh[tid] = g_part[tid];
    __syncthreads();
    if (tid == 0) {
        double si = 0.0, sb = 0.0;
        for (int i = 0; i < NB_RED; i++) { si += sh[i]; sb += sh[NB_RED + i]; }
        double il = si / (double)n_int;
        double bl = sb / (double)n_bnd;
        out[0] = (float)((double)ALPHA * il + bl);
        out[1] = (float)il;
        out[2] = (float)bl;
    }
}

extern "C" void kernel_launch(void* const* d_in, const int* in_sizes, int n_in,
                              void* d_out, int out_size)
{
    const float* xi = (const float*)d_in[0];
    const float* xb = (const float*)d_in[1];
    const float* W0 = (const float*)d_in[2];
    const float* b0 = (const float*)d_in[3];
    const float* W1 = (const float*)d_in[4];
    const float* b1 = (const float*)d_in[5];
    const float* W2 = (const float*)d_in[6];
    const float* b2 = (const float*)d_in[7];
    const float* W3 = (const float*)d_in[8];
    const float* b3 = (const float*)d_in[9];

    int n_int = in_sizes[0] / 2;
    int n_bnd = in_sizes[1] / 2;
    int n_total = n_int + n_bnd;
    int mtiles = (n_total + 31) / 32;

    static int configured = 0;
    if (!configured) {
        cudaFuncSetAttribute(layer_k<0>, cudaFuncAttributeMaxDynamicSharedMemorySize, SMEM_LAYER);
        cudaFuncSetAttribute(layer_k<1>, cudaFuncAttributeMaxDynamicSharedMemorySize, SMEM_LAYER);
        configured = 1;
    }

    prep_all<<<512 + mtiles, 256>>>(xi, xb, W0, b0, W1, W2, n_int, n_bnd);
    dim3 grid(mtiles, 2);
    layer_k<0><<<grid, 256, SMEM_LAYER>>>(0, b1, W3, n_int, n_bnd);
    layer_k<1><<<grid, 256, SMEM_LAYER>>>(1, b2, W3, n_int, n_bnd);
    pinn_partial<<<NB_RED, RED_T>>>(xi, b3, n_int, n_bnd);
    pinn_final<<<1, 128>>>((float*)d_out, n_int, n_bnd);
}

// round 10
// speedup vs baseline: 1.5051x; 1.0259x over previous
#include <cuda_runtime.h>
#include <cuda_bf16.h>
#include <cstdint>
#include <math.h>

typedef unsigned int u32;
typedef unsigned long long u64;

#define HID 512
#define ALPHA 0.01f
#define N_INT_MAX 20000
#define N_BND_MAX 800
#define MT_MAX 656
#define NB_RED 64
#define RED_T 256
#define STAGE_BYTES 49152
#define SMEM_LAYER (4096 + 4 * STAGE_BYTES)

// A operand (jets), bf16 hi/lo, [stage][mtile][128 rows][512 k]
__device__ __nv_bfloat16 gAh[2][(size_t)MT_MAX * 128 * 512];
__device__ __nv_bfloat16 gAl[2][(size_t)MT_MAX * 128 * 512];
// B operand (W^T), bf16 hi/lo, [layer][512 n][512 k]
__device__ __nv_bfloat16 gBh[2][512 * 512];
__device__ __nv_bfloat16 gBl[2][512 * 512];
// per-nhalf partials
__device__ float g_lp[2][N_INT_MAX];
__device__ float g_up[2][N_BND_MAX];
__device__ double g_part[2 * NB_RED];

// ---------------- helpers ----------------
__device__ __forceinline__ void cp16(u32 dst, const void* src) {
    asm volatile("cp.async.cg.shared.global [%0], [%1], 16;" :: "r"(dst), "l"(src));
}
__device__ __forceinline__ void cp_commit() { asm volatile("cp.async.commit_group;"); }
__device__ __forceinline__ void cp_wait2()  { asm volatile("cp.async.wait_group 2;"); }
__device__ __forceinline__ void cp_wait1()  { asm volatile("cp.async.wait_group 1;"); }
__device__ __forceinline__ void cp_wait0()  { asm volatile("cp.async.wait_group 0;"); }

__device__ __forceinline__ void ldsm4(u32& r0, u32& r1, u32& r2, u32& r3, u32 addr) {
    asm volatile("ldmatrix.sync.aligned.m8n8.x4.shared.b16 {%0,%1,%2,%3}, [%4];"
        : "=r"(r0), "=r"(r1), "=r"(r2), "=r"(r3) : "r"(addr));
}
__device__ __forceinline__ void mma_bf16(float* c, const u32* a, u32 b0, u32 b1) {
    asm volatile("mma.sync.aligned.m16n8k16.row.col.f32.bf16.bf16.f32 "
        "{%0,%1,%2,%3}, {%4,%5,%6,%7}, {%8,%9}, {%0,%1,%2,%3};"
        : "+f"(c[0]), "+f"(c[1]), "+f"(c[2]), "+f"(c[3])
        : "r"(a[0]), "r"(a[1]), "r"(a[2]), "r"(a[3]), "r"(b0), "r"(b1));
}
__device__ __forceinline__ void split_bf16(float v, __nv_bfloat16& hi, __nv_bfloat16& lo) {
    hi = __float2bfloat16_rn(v);
    lo = __float2bfloat16_rn(v - __bfloat162float(hi));
}
__device__ __forceinline__ u32 pack_bf2(__nv_bfloat16 a, __nv_bfloat16 b) {
    return (u32)__bfloat16_as_ushort(a) | ((u32)__bfloat16_as_ushort(b) << 16);
}

// ---------------- fused prep: W transpose-split (512 blocks) + layer-0 jets ----------------
__global__ void __launch_bounds__(256) prep_all(
    const float* __restrict__ xi, const float* __restrict__ xb,
    const float* __restrict__ W0, const float* __restrict__ b0,
    const float* __restrict__ W1, const float* __restrict__ W2,
    int n_int, int n_bnd)
{
    __shared__ float sm[32][33];
    __shared__ float s_wx[512], s_wy[512], s_b[512], s_x[32], s_y[32];
    const int tid = threadIdx.x;

    if (blockIdx.x < 512) {
        int b = blockIdx.x;
        int l = b >> 8, rem = b & 255;
        int kt = rem & 15, nt = rem >> 4;
        const float* W = l ? W2 : W1;
        int tx = tid & 31, ty = tid >> 5;
        #pragma unroll
        for (int i = 0; i < 4; i++)
            sm[ty + 8 * i][tx] = W[(size_t)(kt * 32 + ty + 8 * i) * 512 + nt * 32 + tx];
        __syncthreads();
        #pragma unroll
        for (int i = 0; i < 4; i++) {
            int n = nt * 32 + ty + 8 * i;
            int k = kt * 32 + tx;
            float v = sm[tx][ty + 8 * i];
            __nv_bfloat16 hi, lo; split_bf16(v, hi, lo);
            gBh[l][(size_t)n * 512 + k] = hi;
            gBl[l][(size_t)n * 512 + k] = lo;
        }
        return;
    }

    const int mt = blockIdx.x - 512;
    for (int i = tid; i < 512; i += 256) {
        s_wx[i] = W0[i]; s_wy[i] = W0[512 + i]; s_b[i] = b0[i];
    }
    if (tid < 32) {
        int gp = mt * 32 + tid;
        float x = 0.f, y = 0.f;
        if (gp < n_int) { x = xi[2 * gp]; y = xi[2 * gp + 1]; }
        else if (gp < n_int + n_bnd) { x = xb[2 * (gp - n_int)]; y = xb[2 * (gp - n_int) + 1]; }
        s_x[tid] = x; s_y[tid] = y;
    }
    __syncthreads();
    u32* Oh = (u32*)(gAh[0] + (size_t)mt * 65536);
    u32* Ol = (u32*)(gAl[0] + (size_t)mt * 65536);
    for (int it = tid; it < 32 * 256; it += 256) {
        int p = it >> 8, n2 = it & 255;
        float cj[2][4];
        #pragma unroll
        for (int e = 0; e < 2; e++) {
            int n = 2 * n2 + e;
            float wx = s_wx[n], wy = s_wy[n];
            float z = fmaf(s_x[p], wx, fmaf(s_y[p], wy, s_b[n]));
            float tt = tanhf(z), sd = 1.f - tt * tt;
            cj[e][0] = tt; cj[e][1] = sd * wx; cj[e][2] = sd * wy;
            cj[e][3] = -2.f * tt * sd * (wx * wx + wy * wy);
        }
        #pragma unroll
        for (int cc = 0; cc < 4; cc++) {
            __nv_bfloat16 h0, l0, h1, l1;
            split_bf16(cj[0][cc], h0, l0);
            split_bf16(cj[1][cc], h1, l1);
            u32 off = (u32)(4 * p + cc) * 256 + n2;
            Oh[off] = pack_bf2(h0, h1);
            Ol[off] = pack_bf2(l0, l1);
        }
    }
}

// ---------------- main GEMM layer (mma.sync bf16, 3-product split) ----------------
// grid (mtiles, 2). 512 threads = 16 warps (4M x 4N); warp tile M32 x N64.
// 4-stage ring, K-chunk 32. Stage (48KB):
//   Ah: ch*2048 + row*16   (128 rows x 4 ch, 8KB)   @ +0
//   Al: same               @ +8192
//   Bh: ch*4096 + row*16   (256 rows x 4 ch, 16KB)  @ +16384
//   Bl: same               @ +32768
template<int FINAL>
__global__ void __launch_bounds__(512, 1) layer_k(
    int sIn, const float* __restrict__ bias, const float* __restrict__ W3,
    int n_int, int n_bnd)
{
    extern __shared__ float smem[];
    u32 sb = (u32)__cvta_generic_to_shared(smem);
    const int tid = threadIdx.x, lane = tid & 31, w = tid >> 5;
    const int warpM = w & 3, warpN = w >> 2;     // 4 x 4
    const int mt = blockIdx.x, nhalf = blockIdx.y;

    float* s_bias = smem;          // 256
    float* s_w3   = smem + 256;    // 256
    float* s_red  = smem + 512;    // 256

    if (tid < 256) {
        s_bias[tid] = bias[nhalf * 256 + tid];
        if (FINAL) s_w3[tid] = W3[nhalf * 256 + tid];
    }

    const char* Ah = (const char*)(gAh[sIn] + (size_t)mt * 65536);
    const char* Al = (const char*)(gAl[sIn] + (size_t)mt * 65536);
    const char* Bh = (const char*)(gBh[sIn] + (size_t)nhalf * 256 * 512);
    const char* Bl = (const char*)(gBl[sIn] + (size_t)nhalf * 256 * 512);

    auto fill = [&](int kt) {
        u32 base = sb + 4096u + (u32)(kt & 3) * (u32)STAGE_BYTES;
        // A: 128 rows x 4 chunks (hi+lo): 512 threads -> 1 each
        {
            int ch = tid & 3, row = tid >> 2;
            u32 d = base + (u32)ch * 2048u + (u32)row * 16u;
            size_t s = (size_t)row * 1024 + (size_t)kt * 64 + (size_t)ch * 16;
            cp16(d,          Ah + s);
            cp16(d + 8192u,  Al + s);
        }
        // B: 256 rows x 4 chunks (hi+lo): 2 each
        #pragma unroll
        for (int i = 0; i < 2; i++) {
            int u = tid + i * 512;
            int ch = u & 3, row = u >> 2;
            u32 d = base + 16384u + (u32)ch * 4096u + (u32)row * 16u;
            size_t s = (size_t)row * 1024 + (size_t)kt * 64 + (size_t)ch * 16;
            cp16(d,           Bh + s);
            cp16(d + 16384u,  Bl + s);
        }
    };

    float acc[2][8][4];
    #pragma unroll
    for (int mi = 0; mi < 2; mi++)
        #pragma unroll
        for (int ni = 0; ni < 8; ni++)
            #pragma unroll
            for (int r = 0; r < 4; r++) acc[mi][ni][r] = 0.f;

    fill(0); cp_commit();
    fill(1); cp_commit();
    fill(2); cp_commit();

    const int rowA = (lane & 7) + (lane & 8);          // + warpM*32 + mi*16
    const int chAh = (lane >> 4) & 1;
    const int rowB = (lane & 7) + ((lane & 16) >> 1);  // + warpN*64 + ni2*16
    const int chBh = (lane >> 3) & 1;

    #pragma unroll 1
    for (int kt = 0; kt < 16; kt++) {
        if (kt <= 13) cp_wait2();
        else if (kt == 14) cp_wait1();
        else cp_wait0();
        __syncthreads();
        if (kt + 3 < 16) { fill(kt + 3); cp_commit(); }

        u32 tb = sb + 4096u + (u32)(kt & 3) * (u32)STAGE_BYTES;
        #pragma unroll
        for (int ks = 0; ks < 2; ks++) {
            u32 ah[2][4], al[2][4];
            #pragma unroll
            for (int mi = 0; mi < 2; mi++) {
                int row = warpM * 32 + mi * 16 + rowA;
                u32 ad = tb + (u32)(ks * 2 + chAh) * 2048u + (u32)row * 16u;
                ldsm4(ah[mi][0], ah[mi][1], ah[mi][2], ah[mi][3], ad);
                ldsm4(al[mi][0], al[mi][1], al[mi][2], al[mi][3], ad + 8192u);
            }
            #pragma unroll
            for (int ni2 = 0; ni2 < 4; ni2++) {
                int row = warpN * 64 + ni2 * 16 + rowB;
                u32 bd = tb + 16384u + (u32)(ks * 2 + chBh) * 4096u + (u32)row * 16u;
                u32 bh[4], bl[4];
                ldsm4(bh[0], bh[1], bh[2], bh[3], bd);
                ldsm4(bl[0], bl[1], bl[2], bl[3], bd + 16384u);
                #pragma unroll
                for (int mi = 0; mi < 2; mi++) {
                    float* c0 = acc[mi][ni2 * 2];
                    float* c1 = acc[mi][ni2 * 2 + 1];
                    mma_bf16(c0, ah[mi], bh[0], bh[1]);
                    mma_bf16(c0, al[mi], bh[0], bh[1]);
                    mma_bf16(c0, ah[mi], bl[0], bl[1]);
                    mma_bf16(c1, ah[mi], bh[2], bh[3]);
                    mma_bf16(c1, al[mi], bh[2], bh[3]);
                    mma_bf16(c1, ah[mi], bl[2], bl[3]);
                }
            }
        }
    }

    // ---------------- epilogue ----------------
    const int t4 = lane & 3;
    const int gg = lane >> 2;
    const int cmy = gg & 3;
    const int baseLane = lane & 0x13;
    float du[4] = {0.f, 0.f, 0.f, 0.f};
    float dl[4] = {0.f, 0.f, 0.f, 0.f};
    u32* Oh = (u32*)(gAh[sIn ^ 1] + (size_t)mt * 65536);
    u32* Ol = (u32*)(gAl[sIn ^ 1] + (size_t)mt * 65536);

    #pragma unroll
    for (int mi = 0; mi < 2; mi++) {
        #pragma unroll
        for (int rh = 0; rh < 2; rh++) {
            int R = warpM * 32 + mi * 16 + rh * 8 + gg;
            #pragma unroll
            for (int ni = 0; ni < 8; ni++) {
                float vv[2];
                #pragma unroll
                for (int ch = 0; ch < 2; ch++) {
                    float z = acc[mi][ni][rh * 2 + ch];
                    float zv  = __shfl_sync(0xffffffffu, z, baseLane);
                    float zgx = __shfl_sync(0xffffffffu, z, baseLane | 4);
                    float zgy = __shfl_sync(0xffffffffu, z, baseLane | 8);
                    float zL  = __shfl_sync(0xffffffffu, z, baseLane | 12);
                    int n_loc = warpN * 64 + ni * 8 + 2 * t4 + ch;
                    float tt = tanhf(zv + s_bias[n_loc]);
                    float sd = 1.f - tt * tt;
                    float Lo = fmaf(sd, zL, -2.f * tt * sd * (zgx * zgx + zgy * zgy));
                    if (FINAL) {
                        float w3 = s_w3[n_loc];
                        du[mi * 2 + rh] = fmaf(tt, w3, du[mi * 2 + rh]);
                        dl[mi * 2 + rh] = fmaf(Lo, w3, dl[mi * 2 + rh]);
                    } else {
                        vv[ch] = (cmy == 0) ? tt : (cmy == 1) ? sd * zgx
                               : (cmy == 2) ? sd * zgy : Lo;
                    }
                }
                if (!FINAL) {
                    __nv_bfloat16 h0, l0, h1, l1;
                    split_bf16(vv[0], h0, l0);
                    split_bf16(vv[1], h1, l1);
                    u32 eo = (u32)R * 256 + (u32)(nhalf * 256 + warpN * 64 + ni * 8 + 2 * t4) / 2;
                    Oh[eo] = pack_bf2(h0, h1);
                    Ol[eo] = pack_bf2(l0, l1);
                }
            }
        }
    }

    if (FINAL) {
        #pragma unroll
        for (int s = 0; s < 4; s++) {
            du[s] += __shfl_xor_sync(0xffffffffu, du[s], 1);
            du[s] += __shfl_xor_sync(0xffffffffu, du[s], 2);
            dl[s] += __shfl_xor_sync(0xffffffffu, dl[s], 1);
            dl[s] += __shfl_xor_sync(0xffffffffu, dl[s], 2);
        }
        float* s_u = s_red;            // [warpN*32 + p], 128
        float* s_l = s_red + 128;      // 128
        if (lane == 0 || lane == 16) {
            int ghi = lane >> 4;
            #pragma unroll
            for (int mi = 0; mi < 2; mi++)
                #pragma unroll
                for (int rh = 0; rh < 2; rh++) {
                    int p = warpM * 8 + mi * 4 + rh * 2 + ghi;
                    if (warpN == 0) { s_u[p] = du[mi * 2 + rh]; s_l[p] = dl[mi * 2 + rh]; }
                }
        }
        __syncthreads();
        // accumulate warpN 1..3 into shared (serialized by warpN to stay deterministic)
        for (int q = 1; q < 4; q++) {
            if (warpN == q && (lane == 0 || lane == 16)) {
                int ghi = lane >> 4;
                #pragma unroll
                for (int mi = 0; mi < 2; mi++)
                    #pragma unroll
                    for (int rh = 0; rh < 2; rh++) {
                        int p = warpM * 8 + mi * 4 + rh * 2 + ghi;
                        s_u[p] += du[mi * 2 + rh];
                        s_l[p] += dl[mi * 2 + rh];
                    }
            }
            __syncthreads();
        }
        if (tid < 32) {
            int pt = mt * 32 + tid;
            if (pt < n_int) g_lp[nhalf][pt] = s_l[tid];
            else if (pt < n_int + n_bnd) g_up[nhalf][pt - n_int] = s_u[tid];
        }
    }
}

// ---------------- two-stage deterministic reduction ----------------
__global__ void pinn_partial(const float* __restrict__ xi, const float* __restrict__ b3,
                             int n_int, int n_bnd)
{
    __shared__ double sh[2 * RED_T];
    const int tid = threadIdx.x;
    const int stride = NB_RED * RED_T;
    const float PI = 3.14159265358979f;
    float b3v = b3[0];

    double si = 0.0, sb = 0.0;
    for (int i = blockIdx.x * RED_T + tid; i < n_int; i += stride) {
        float xx = xi[2 * i], yy = xi[2 * i + 1];
        float y2 = yy * yy;
        float sp = sinf(PI * xx);
        float s2, c2; sincosf(PI * y2, &s2, &c2);
        float f = -PI * PI * (1.0f + 4.0f * y2) * sp * s2 + 2.0f * PI * sp * c2;
        float r = (g_lp[0][i] + g_lp[1][i]) - f;
        si += (double)r * r;
    }
    for (int i = blockIdx.x * RED_T + tid; i < n_bnd; i += stride) {
        float u = g_up[0][i] + g_up[1][i] + b3v;
        sb += (double)u * u;
    }
    sh[tid] = si; sh[RED_T + tid] = sb;
    __syncthreads();
    for (int s = RED_T / 2; s > 0; s >>= 1) {
        if (tid < s) { sh[tid] += sh[tid + s]; sh[RED_T + tid] += sh[RED_T + tid + s]; }
        __syncthreads();
    }
    if (tid == 0) {
        g_part[blockIdx.x] = sh[0];
        g_part[NB_RED + blockIdx.x] = sh[RED_T];
    }
}

__global__ void pinn_final(float* __restrict__ out, int n_int, int n_bnd)
{
    __shared__ double sh[2 * NB_RED];
    int tid = threadIdx.x;
    if (tid < 2 * NB_RED) sh[tid] = g_part[tid];
    __syncthreads();
    if (tid == 0) {
        double si = 0.0, sb = 0.0;
        for (int i = 0; i < NB_RED; i++) { si += sh[i]; sb += sh[NB_RED + i]; }
        double il = si / (double)n_int;
        double bl = sb / (double)n_bnd;
        out[0] = (float)((double)ALPHA * il + bl);
        out[1] = (float)il;
        out[2] = (float)bl;
    }
}

extern "C" void kernel_launch(void* const* d_in, const int* in_sizes, int n_in,
                              void* d_out, int out_size)
{
    const float* xi = (const float*)d_in[0];
    const float* xb = (const float*)d_in[1];
    const float* W0 = (const float*)d_in[2];
    const float* b0 = (const float*)d_in[3];
    const float* W1 = (const float*)d_in[4];
    const float* b1 = (const float*)d_in[5];
    const float* W2 = (const float*)d_in[6];
    const float* b2 = (const float*)d_in[7];
    const float* W3 = (const float*)d_in[8];
    const float* b3 = (const float*)d_in[9];

    int n_int = in_sizes[0] / 2;
    int n_bnd = in_sizes[1] / 2;
    int n_total = n_int + n_bnd;
    int mtiles = (n_total + 31) / 32;

    static int configured = 0;
    if (!configured) {
        cudaFuncSetAttribute(layer_k<0>, cudaFuncAttributeMaxDynamicSharedMemorySize, SMEM_LAYER);
        cudaFuncSetAttribute(layer_k<1>, cudaFuncAttributeMaxDynamicSharedMemorySize, SMEM_LAYER);
        configured = 1;
    }

    prep_all<<<512 + mtiles, 256>>>(xi, xb, W0, b0, W1, W2, n_int, n_bnd);
    dim3 grid(mtiles, 2);
    layer_k<0><<<grid, 512, SMEM_LAYER>>>(0, b1, W3, n_int, n_bnd);
    layer_k<1><<<grid, 512, SMEM_LAYER>>>(1, b2, W3, n_int, n_bnd);
    pinn_partial<<<NB_RED, RED_T>>>(xi, b3, n_int, n_bnd);
    pinn_final<<<1, 128>>>((float*)d_out, n_int, n_bnd);
}

// round 14
// speedup vs baseline: 2.2826x; 1.5166x over previous
#include <cuda_runtime.h>
#include <cuda_fp16.h>
#include <cstdint>
#include <math.h>

typedef unsigned int u32;
typedef unsigned long long u64;

#define HID 512
#define ALPHA 0.01f
#define N_INT_MAX 20000
#define N_BND_MAX 800
#define MT_MAX 640
#define NB_RED 64
#define RED_T 256
#define STAGE_BYTES 24576
#define SMEM_LAYER (4096 + 4 * STAGE_BYTES)
#define BPT 8

// A operand (jets), fp16, [stage][mtile][128 rows][512 k]
__device__ __half gA[2][(size_t)MT_MAX * 128 * 512];
// B operand (W^T), fp16, [layer][512 n][512 k]
__device__ __half gB[2][512 * 512];
// per-nhalf laplacian partials (interior), fp32 boundary values
__device__ float g_lp[2][N_INT_MAX];
__device__ float g_ub[N_BND_MAX];
__device__ double g_part[2 * NB_RED];

// ---------------- helpers ----------------
__device__ __forceinline__ void cp16(u32 dst, const void* src) {
    asm volatile("cp.async.cg.shared.global [%0], [%1], 16;" :: "r"(dst), "l"(src));
}
__device__ __forceinline__ void cp_commit() { asm volatile("cp.async.commit_group;"); }
__device__ __forceinline__ void cp_wait2()  { asm volatile("cp.async.wait_group 2;"); }
__device__ __forceinline__ void cp_wait1()  { asm volatile("cp.async.wait_group 1;"); }
__device__ __forceinline__ void cp_wait0()  { asm volatile("cp.async.wait_group 0;"); }

__device__ __forceinline__ void ldsm4(u32& r0, u32& r1, u32& r2, u32& r3, u32 addr) {
    asm volatile("ldmatrix.sync.aligned.m8n8.x4.shared.b16 {%0,%1,%2,%3}, [%4];"
        : "=r"(r0), "=r"(r1), "=r"(r2), "=r"(r3) : "r"(addr));
}
__device__ __forceinline__ void mma_f16(float* c, const u32* a, u32 b0, u32 b1) {
    asm volatile("mma.sync.aligned.m16n8k16.row.col.f32.f16.f16.f32 "
        "{%0,%1,%2,%3}, {%4,%5,%6,%7}, {%8,%9}, {%0,%1,%2,%3};"
        : "+f"(c[0]), "+f"(c[1]), "+f"(c[2]), "+f"(c[3])
        : "r"(a[0]), "r"(a[1]), "r"(a[2]), "r"(a[3]), "r"(b0), "r"(b1));
}
__device__ __forceinline__ u32 pack_h2(float a, float b) {
    __half2 h = __floats2half2_rn(a, b);
    return *(u32*)&h;
}

// ---------------- fused prep: W transpose (512 blocks) + layer-0 jets (interior) ----------------
__global__ void __launch_bounds__(256) prep_all(
    const float* __restrict__ xi,
    const float* __restrict__ W0, const float* __restrict__ b0,
    const float* __restrict__ W1, const float* __restrict__ W2,
    int n_int)
{
    __shared__ float sm[32][33];
    __shared__ float s_wx[512], s_wy[512], s_b[512], s_x[32], s_y[32];
    const int tid = threadIdx.x;

    if (blockIdx.x < 512) {
        int b = blockIdx.x;
        int l = b >> 8, rem = b & 255;
        int kt = rem & 15, nt = rem >> 4;
        const float* W = l ? W2 : W1;
        int tx = tid & 31, ty = tid >> 5;
        #pragma unroll
        for (int i = 0; i < 4; i++)
            sm[ty + 8 * i][tx] = W[(size_t)(kt * 32 + ty + 8 * i) * 512 + nt * 32 + tx];
        __syncthreads();
        #pragma unroll
        for (int i = 0; i < 4; i++) {
            int n = nt * 32 + ty + 8 * i;
            int k = kt * 32 + tx;
            gB[l][(size_t)n * 512 + k] = __float2half_rn(sm[tx][ty + 8 * i]);
        }
        return;
    }

    const int mt = blockIdx.x - 512;
    for (int i = tid; i < 512; i += 256) {
        s_wx[i] = W0[i]; s_wy[i] = W0[512 + i]; s_b[i] = b0[i];
    }
    if (tid < 32) {
        int gp = mt * 32 + tid;
        float x = 0.f, y = 0.f;
        if (gp < n_int) { x = xi[2 * gp]; y = xi[2 * gp + 1]; }
        s_x[tid] = x; s_y[tid] = y;
    }
    __syncthreads();
    u32* O = (u32*)(gA[0] + (size_t)mt * 65536);
    for (int it = tid; it < 32 * 256; it += 256) {
        int p = it >> 8, n2 = it & 255;
        float cj[2][4];
        #pragma unroll
        for (int e = 0; e < 2; e++) {
            int n = 2 * n2 + e;
            float wx = s_wx[n], wy = s_wy[n];
            float z = fmaf(s_x[p], wx, fmaf(s_y[p], wy, s_b[n]));
            float tt = tanhf(z), sd = 1.f - tt * tt;
            cj[e][0] = tt; cj[e][1] = sd * wx; cj[e][2] = sd * wy;
            cj[e][3] = -2.f * tt * sd * (wx * wx + wy * wy);
        }
        #pragma unroll
        for (int cc = 0; cc < 4; cc++)
            O[(u32)(4 * p + cc) * 256 + n2] = pack_h2(cj[0][cc], cj[1][cc]);
    }
}

// ---------------- exact fp32 boundary values (800 points, value-only MLP) ----------------
__global__ void __launch_bounds__(256) boundary_k(
    const float* __restrict__ xb,
    const float* __restrict__ W0, const float* __restrict__ b0,
    const float* __restrict__ W1, const float* __restrict__ b1,
    const float* __restrict__ W2, const float* __restrict__ b2,
    const float* __restrict__ W3, const float* __restrict__ b3,
    int n_bnd)
{
    __shared__ float act[2][BPT][512];
    __shared__ float s_x[BPT], s_y[BPT];
    const int tid = threadIdx.x;
    const int p0 = blockIdx.x * BPT;

    if (tid < BPT) {
        int pt = p0 + tid;
        float x = 0.f, y = 0.f;
        if (pt < n_bnd) { x = xb[2 * pt]; y = xb[2 * pt + 1]; }
        s_x[tid] = x; s_y[tid] = y;
    }
    __syncthreads();

    // layer 0
    #pragma unroll
    for (int jj = 0; jj < 2; jj++) {
        int j = tid + jj * 256;
        float wx = W0[j], wy = W0[512 + j], bb = b0[j];
        #pragma unroll
        for (int p = 0; p < BPT; p++)
            act[0][p][j] = tanhf(fmaf(s_x[p], wx, fmaf(s_y[p], wy, bb)));
    }
    __syncthreads();

    // hidden layers 1,2
    #pragma unroll 1
    for (int L = 0; L < 2; L++) {
        const float* __restrict__ W = L ? W2 : W1;
        const float* __restrict__ bs = L ? b2 : b1;
        float acc[BPT][2];
        #pragma unroll
        for (int p = 0; p < BPT; p++) { acc[p][0] = 0.f; acc[p][1] = 0.f; }
        #pragma unroll 4
        for (int k = 0; k < 512; k++) {
            float wa = W[(size_t)k * 512 + tid];
            float wb = W[(size_t)k * 512 + tid + 256];
            #pragma unroll
            for (int p = 0; p < BPT; p++) {
                float a = act[L & 1][p][k];
                acc[p][0] = fmaf(a, wa, acc[p][0]);
                acc[p][1] = fmaf(a, wb, acc[p][1]);
            }
        }
        float ba = bs[tid], bb = bs[tid + 256];
        #pragma unroll
        for (int p = 0; p < BPT; p++) {
            act[(L & 1) ^ 1][p][tid]       = tanhf(acc[p][0] + ba);
            act[(L & 1) ^ 1][p][tid + 256] = tanhf(acc[p][1] + bb);
        }
        __syncthreads();
    }

    // output: warp w handles point w
    const int wp = tid >> 5, lane = tid & 31;
    float s = 0.f;
    #pragma unroll
    for (int i = 0; i < 16; i++) {
        int k = lane + 32 * i;
        s = fmaf(act[0][wp][k], W3[k], s);
    }
    #pragma unroll
    for (int off = 16; off; off >>= 1)
        s += __shfl_down_sync(0xffffffffu, s, off);
    if (lane == 0 && p0 + wp < n_bnd)
        g_ub[p0 + wp] = s + b3[0];
}

// ---------------- main GEMM layer (plain fp16 mma.sync, fp32 accum) ----------------
// grid (mtiles, 2). 512 threads = 16 warps (4M x 4N); warp tile M32 x N64.
// 4-stage ring, K-chunk 32. Stage (24KB): A 8KB @+0, B 16KB @+8192.
template<int FINAL>
__global__ void __launch_bounds__(512, 1) layer_k(
    int sIn, const float* __restrict__ bias, const float* __restrict__ W3,
    int n_int)
{
    extern __shared__ float smem[];
    u32 sb = (u32)__cvta_generic_to_shared(smem);
    const int tid = threadIdx.x, lane = tid & 31, w = tid >> 5;
    const int warpM = w & 3, warpN = w >> 2;
    const int mt = blockIdx.x, nhalf = blockIdx.y;

    float* s_bias = smem;          // 256
    float* s_w3   = smem + 256;    // 256
    float* s_red  = smem + 512;    // 128

    if (tid < 256) {
        s_bias[tid] = bias[nhalf * 256 + tid];
        if (FINAL) s_w3[tid] = W3[nhalf * 256 + tid];
    }

    const char* A = (const char*)(gA[sIn] + (size_t)mt * 65536);
    const char* B = (const char*)(gB[sIn] + (size_t)nhalf * 256 * 512);

    auto fill = [&](int kt) {
        u32 base = sb + 4096u + (u32)(kt & 3) * (u32)STAGE_BYTES;
        {
            int ch = tid & 3, row = tid >> 2;
            u32 d = base + (u32)ch * 2048u + (u32)row * 16u;
            cp16(d, A + (size_t)row * 1024 + (size_t)kt * 64 + (size_t)ch * 16);
        }
        #pragma unroll
        for (int i = 0; i < 2; i++) {
            int u = tid + i * 512;
            int ch = u & 3, row = u >> 2;
            u32 d = base + 8192u + (u32)ch * 4096u + (u32)row * 16u;
            cp16(d, B + (size_t)row * 1024 + (size_t)kt * 64 + (size_t)ch * 16);
        }
    };

    float acc[2][8][4];
    #pragma unroll
    for (int mi = 0; mi < 2; mi++)
        #pragma unroll
        for (int ni = 0; ni < 8; ni++)
            #pragma unroll
            for (int r = 0; r < 4; r++) acc[mi][ni][r] = 0.f;

    fill(0); cp_commit();
    fill(1); cp_commit();
    fill(2); cp_commit();

    const int rowA = (lane & 7) + (lane & 8);
    const int chAh = (lane >> 4) & 1;
    const int rowB = (lane & 7) + ((lane & 16) >> 1);
    const int chBh = (lane >> 3) & 1;

    #pragma unroll 1
    for (int kt = 0; kt < 16; kt++) {
        if (kt <= 13) cp_wait2();
        else if (kt == 14) cp_wait1();
        else cp_wait0();
        __syncthreads();
        if (kt + 3 < 16) { fill(kt + 3); cp_commit(); }

        u32 tb = sb + 4096u + (u32)(kt & 3) * (u32)STAGE_BYTES;
        #pragma unroll
        for (int ks = 0; ks < 2; ks++) {
            u32 ah[2][4];
            #pragma unroll
            for (int mi = 0; mi < 2; mi++) {
                int row = warpM * 32 + mi * 16 + rowA;
                u32 ad = tb + (u32)(ks * 2 + chAh) * 2048u + (u32)row * 16u;
                ldsm4(ah[mi][0], ah[mi][1], ah[mi][2], ah[mi][3], ad);
            }
            #pragma unroll
            for (int ni2 = 0; ni2 < 4; ni2++) {
                int row = warpN * 64 + ni2 * 16 + rowB;
                u32 bd = tb + 8192u + (u32)(ks * 2 + chBh) * 4096u + (u32)row * 16u;
                u32 bh[4];
                ldsm4(bh[0], bh[1], bh[2], bh[3], bd);
                #pragma unroll
                for (int mi = 0; mi < 2; mi++) {
                    mma_f16(acc[mi][ni2 * 2],     ah[mi], bh[0], bh[1]);
                    mma_f16(acc[mi][ni2 * 2 + 1], ah[mi], bh[2], bh[3]);
                }
            }
        }
    }

    // ---------------- epilogue ----------------
    const int t4 = lane & 3;
    const int gg = lane >> 2;
    const int cmy = gg & 3;
    const int baseLane = lane & 0x13;
    float dl[4] = {0.f, 0.f, 0.f, 0.f};
    u32* O = (u32*)(gA[sIn ^ 1] + (size_t)mt * 65536);

    #pragma unroll
    for (int mi = 0; mi < 2; mi++) {
        #pragma unroll
        for (int rh = 0; rh < 2; rh++) {
            int R = warpM * 32 + mi * 16 + rh * 8 + gg;
            #pragma unroll
            for (int ni = 0; ni < 8; ni++) {
                float vv[2];
                #pragma unroll
                for (int ch = 0; ch < 2; ch++) {
                    float z = acc[mi][ni][rh * 2 + ch];
                    float zv  = __shfl_sync(0xffffffffu, z, baseLane);
                    float zgx = __shfl_sync(0xffffffffu, z, baseLane | 4);
                    float zgy = __shfl_sync(0xffffffffu, z, baseLane | 8);
                    float zL  = __shfl_sync(0xffffffffu, z, baseLane | 12);
                    int n_loc = warpN * 64 + ni * 8 + 2 * t4 + ch;
                    float tt = tanhf(zv + s_bias[n_loc]);
                    float sd = 1.f - tt * tt;
                    float Lo = fmaf(sd, zL, -2.f * tt * sd * (zgx * zgx + zgy * zgy));
                    if (FINAL) {
                        dl[mi * 2 + rh] = fmaf(Lo, s_w3[n_loc], dl[mi * 2 + rh]);
                    } else {
                        vv[ch] = (cmy == 0) ? tt : (cmy == 1) ? sd * zgx
                               : (cmy == 2) ? sd * zgy : Lo;
                    }
                }
                if (!FINAL) {
                    u32 eo = (u32)R * 256 + (u32)(nhalf * 256 + warpN * 64 + ni * 8 + 2 * t4) / 2;
                    O[eo] = pack_h2(vv[0], vv[1]);
                }
            }
        }
    }

    if (FINAL) {
        #pragma unroll
        for (int s = 0; s < 4; s++) {
            dl[s] += __shfl_xor_sync(0xffffffffu, dl[s], 1);
            dl[s] += __shfl_xor_sync(0xffffffffu, dl[s], 2);
        }
        float* s_l = s_red;      // 128 (only laplacian; comp lanes gg&3==3 matter)
        if (lane == 0 || lane == 16) {
            int ghi = lane >> 4;
            #pragma unroll
            for (int mi = 0; mi < 2; mi++)
                #pragma unroll
                for (int rh = 0; rh < 2; rh++) {
                    int p = warpM * 8 + mi * 4 + rh * 2 + ghi;
                    if (warpN == 0) s_l[p] = dl[mi * 2 + rh];
                }
        }
        __syncthreads();
        for (int q = 1; q < 4; q++) {
            if (warpN == q && (lane == 0 || lane == 16)) {
                int ghi = lane >> 4;
                #pragma unroll
                for (int mi = 0; mi < 2; mi++)
                    #pragma unroll
                    for (int rh = 0; rh < 2; rh++) {
                        int p = warpM * 8 + mi * 4 + rh * 2 + ghi;
                        s_l[p] += dl[mi * 2 + rh];
                    }
            }
            __syncthreads();
        }
        if (tid < 32) {
            int pt = mt * 32 + tid;
            if (pt < n_int) g_lp[nhalf][pt] = s_l[tid];
        }
    }
}

// ---------------- two-stage deterministic reduction ----------------
__global__ void pinn_partial(const float* __restrict__ xi, int n_int, int n_bnd)
{
    __shared__ double sh[2 * RED_T];
    const int tid = threadIdx.x;
    const int stride = NB_RED * RED_T;
    const float PI = 3.14159265358979f;

    double si = 0.0, sb = 0.0;
    for (int i = blockIdx.x * RED_T + tid; i < n_int; i += stride) {
        float xx = xi[2 * i], yy = xi[2 * i + 1];
        float y2 = yy * yy;
        float sp = sinf(PI * xx);
        float s2, c2; sincosf(PI * y2, &s2, &c2);
        float f = -PI * PI * (1.0f + 4.0f * y2) * sp * s2 + 2.0f * PI * sp * c2;
        float r = (g_lp[0][i] + g_lp[1][i]) - f;
        si += (double)r * r;
    }
    for (int i = blockIdx.x * RED_T + tid; i < n_bnd; i += stride) {
        float u = g_ub[i];
        sb += (double)u * u;
    }
    sh[tid] = si; sh[RED_T + tid] = sb;
    __syncthreads();
    for (int s = RED_T / 2; s > 0; s >>= 1) {
        if (tid < s) { sh[tid] += sh[tid + s]; sh[RED_T + tid] += sh[RED_T + tid + s]; }
        __syncthreads();
    }
    if (tid == 0) {
        g_part[blockIdx.x] = sh[0];
        g_part[NB_RED + blockIdx.x] = sh[RED_T];
    }
}

__global__ void pinn_final(float* __restrict__ out, int n_int, int n_bnd)
{
    __shared__ double sh[2 * NB_RED];
    int tid = threadIdx.x;
    if (tid < 2 * NB_RED) sh[tid] = g_part[tid];
    __syncthreads();
    if (tid == 0) {
        double si = 0.0, sb = 0.0;
        for (int i = 0; i < NB_RED; i++) { si += sh[i]; sb += sh[NB_RED + i]; }
        double il = si / (double)n_int;
        double bl = sb / (double)n_bnd;
        out[0] = (float)((double)ALPHA * il + bl);
        out[1] = (float)il;
        out[2] = (float)bl;
    }
}

extern "C" void kernel_launch(void* const* d_in, const int* in_sizes, int n_in,
                              void* d_out, int out_size)
{
    const float* xi = (const float*)d_in[0];
    const float* xb = (const float*)d_in[1];
    const float* W0 = (const float*)d_in[2];
    const float* b0 = (const float*)d_in[3];
    const float* W1 = (const float*)d_in[4];
    const float* b1 = (const float*)d_in[5];
    const float* W2 = (const float*)d_in[6];
    const float* b2 = (const float*)d_in[7];
    const float* W3 = (const float*)d_in[8];
    const float* b3 = (const float*)d_in[9];

    int n_int = in_sizes[0] / 2;
    int n_bnd = in_sizes[1] / 2;
    int mtiles = (n_int + 31) / 32;
    int bblocks = (n_bnd + BPT - 1) / BPT;

    static int configured = 0;
    if (!configured) {
        cudaFuncSetAttribute(layer_k<0>, cudaFuncAttributeMaxDynamicSharedMemorySize, SMEM_LAYER);
        cudaFuncSetAttribute(layer_k<1>, cudaFuncAttributeMaxDynamicSharedMemorySize, SMEM_LAYER);
        configured = 1;
    }

    prep_all<<<512 + mtiles, 256>>>(xi, W0, b0, W1, W2, n_int);
    boundary_k<<<bblocks, 256>>>(xb, W0, b0, W1, b1, W2, b2, W3, b3, n_bnd);
    dim3 grid(mtiles, 2);
    layer_k<0><<<grid, 512, SMEM_LAYER>>>(0, b1, W3, n_int);
    layer_k<1><<<grid, 512, SMEM_LAYER>>>(1, b2, W3, n_int);
    pinn_partial<<<NB_RED, RED_T>>>(xi, n_int, n_bnd);
    pinn_final<<<1, 128>>>((float*)d_out, n_int, n_bnd);
}

// round 15
// speedup vs baseline: 2.5469x; 1.1158x over previous
#include <cuda_runtime.h>
#include <cuda_fp16.h>
#include <cstdint>
#include <math.h>

typedef unsigned int u32;
typedef unsigned long long u64;

#define HID 512
#define ALPHA 0.01f
#define N_INT_MAX 20000
#define N_BND_MAX 800
#define MT_MAX 640
#define NB_RED 64
#define RED_T 256
#define STAGE_BYTES 24576
#define SMEM_LAYER (4096 + 4 * STAGE_BYTES)
#define BPT 8

// A operand (jets), fp16, [stage][mtile][128 rows][512 k]
__device__ __half gA[2][(size_t)MT_MAX * 128 * 512];
// B operand (W^T), fp16, [layer][512 n][512 k]
__device__ __half gB[2][512 * 512];
// per-nhalf laplacian partials (interior), fp32 boundary values
__device__ float g_lp[2][N_INT_MAX];
__device__ float g_ub[N_BND_MAX];
__device__ double g_part[2 * NB_RED];

// ---------------- helpers ----------------
__device__ __forceinline__ void cp16(u32 dst, const void* src) {
    asm volatile("cp.async.cg.shared.global [%0], [%1], 16;" :: "r"(dst), "l"(src));
}
__device__ __forceinline__ void cp_commit() { asm volatile("cp.async.commit_group;"); }
__device__ __forceinline__ void cp_wait2()  { asm volatile("cp.async.wait_group 2;"); }
__device__ __forceinline__ void cp_wait1()  { asm volatile("cp.async.wait_group 1;"); }
__device__ __forceinline__ void cp_wait0()  { asm volatile("cp.async.wait_group 0;"); }

__device__ __forceinline__ void ldsm4(u32& r0, u32& r1, u32& r2, u32& r3, u32 addr) {
    asm volatile("ldmatrix.sync.aligned.m8n8.x4.shared.b16 {%0,%1,%2,%3}, [%4];"
        : "=r"(r0), "=r"(r1), "=r"(r2), "=r"(r3) : "r"(addr));
}
__device__ __forceinline__ void mma_f16(float* c, const u32* a, u32 b0, u32 b1) {
    asm volatile("mma.sync.aligned.m16n8k16.row.col.f32.f16.f16.f32 "
        "{%0,%1,%2,%3}, {%4,%5,%6,%7}, {%8,%9}, {%0,%1,%2,%3};"
        : "+f"(c[0]), "+f"(c[1]), "+f"(c[2]), "+f"(c[3])
        : "r"(a[0]), "r"(a[1]), "r"(a[2]), "r"(a[3]), "r"(b0), "r"(b1));
}
__device__ __forceinline__ u32 pack_h2(float a, float b) {
    __half2 h = __floats2half2_rn(a, b);
    return *(u32*)&h;
}

// ---------------- fused prep: W transpose (512) + layer-0 jets (mtiles) + boundary (bblocks) ----------------
__global__ void __launch_bounds__(256) prep_all(
    const float* __restrict__ xi, const float* __restrict__ xb,
    const float* __restrict__ W0, const float* __restrict__ b0,
    const float* __restrict__ W1, const float* __restrict__ b1,
    const float* __restrict__ W2, const float* __restrict__ b2,
    const float* __restrict__ W3, const float* __restrict__ b3,
    int n_int, int n_bnd, int mtiles)
{
    __shared__ float sm[32][33];
    __shared__ float s_wx[512], s_wy[512], s_b[512], s_x[32], s_y[32];
    __shared__ float act[2][BPT][512];
    const int tid = threadIdx.x;

    if (blockIdx.x < 512) {
        // ---- transpose W (k-major) -> gB (n-major), fp16 ----
        int b = blockIdx.x;
        int l = b >> 8, rem = b & 255;
        int kt = rem & 15, nt = rem >> 4;
        const float* W = l ? W2 : W1;
        int tx = tid & 31, ty = tid >> 5;
        #pragma unroll
        for (int i = 0; i < 4; i++)
            sm[ty + 8 * i][tx] = W[(size_t)(kt * 32 + ty + 8 * i) * 512 + nt * 32 + tx];
        __syncthreads();
        #pragma unroll
        for (int i = 0; i < 4; i++) {
            int n = nt * 32 + ty + 8 * i;
            int k = kt * 32 + tx;
            gB[l][(size_t)n * 512 + k] = __float2half_rn(sm[tx][ty + 8 * i]);
        }
        return;
    }

    if (blockIdx.x < 512 + mtiles) {
        // ---- layer-0 jets -> A0 (interior points) ----
        const int mt = blockIdx.x - 512;
        for (int i = tid; i < 512; i += 256) {
            s_wx[i] = W0[i]; s_wy[i] = W0[512 + i]; s_b[i] = b0[i];
        }
        if (tid < 32) {
            int gp = mt * 32 + tid;
            float x = 0.f, y = 0.f;
            if (gp < n_int) { x = xi[2 * gp]; y = xi[2 * gp + 1]; }
            s_x[tid] = x; s_y[tid] = y;
        }
        __syncthreads();
        u32* O = (u32*)(gA[0] + (size_t)mt * 65536);
        for (int it = tid; it < 32 * 256; it += 256) {
            int p = it >> 8, n2 = it & 255;
            float cj[2][4];
            #pragma unroll
            for (int e = 0; e < 2; e++) {
                int n = 2 * n2 + e;
                float wx = s_wx[n], wy = s_wy[n];
                float z = fmaf(s_x[p], wx, fmaf(s_y[p], wy, s_b[n]));
                float tt = tanhf(z), sd = 1.f - tt * tt;
                cj[e][0] = tt; cj[e][1] = sd * wx; cj[e][2] = sd * wy;
                cj[e][3] = -2.f * tt * sd * (wx * wx + wy * wy);
            }
            #pragma unroll
            for (int cc = 0; cc < 4; cc++)
                O[(u32)(4 * p + cc) * 256 + n2] = pack_h2(cj[0][cc], cj[1][cc]);
        }
        return;
    }

    // ---- exact fp32 boundary values (value-only MLP) ----
    const int p0 = (blockIdx.x - 512 - mtiles) * BPT;
    if (tid < BPT) {
        int pt = p0 + tid;
        float x = 0.f, y = 0.f;
        if (pt < n_bnd) { x = xb[2 * pt]; y = xb[2 * pt + 1]; }
        s_x[tid] = x; s_y[tid] = y;
    }
    __syncthreads();

    #pragma unroll
    for (int jj = 0; jj < 2; jj++) {
        int j = tid + jj * 256;
        float wx = W0[j], wy = W0[512 + j], bb = b0[j];
        #pragma unroll
        for (int p = 0; p < BPT; p++)
            act[0][p][j] = tanhf(fmaf(s_x[p], wx, fmaf(s_y[p], wy, bb)));
    }
    __syncthreads();

    #pragma unroll 1
    for (int L = 0; L < 2; L++) {
        const float* __restrict__ W = L ? W2 : W1;
        const float* __restrict__ bs = L ? b2 : b1;
        float acc[BPT][2];
        #pragma unroll
        for (int p = 0; p < BPT; p++) { acc[p][0] = 0.f; acc[p][1] = 0.f; }
        #pragma unroll 4
        for (int k = 0; k < 512; k++) {
            float wa = W[(size_t)k * 512 + tid];
            float wb = W[(size_t)k * 512 + tid + 256];
            #pragma unroll
            for (int p = 0; p < BPT; p++) {
                float a = act[L & 1][p][k];
                acc[p][0] = fmaf(a, wa, acc[p][0]);
                acc[p][1] = fmaf(a, wb, acc[p][1]);
            }
        }
        float ba = bs[tid], bb = bs[tid + 256];
        #pragma unroll
        for (int p = 0; p < BPT; p++) {
            act[(L & 1) ^ 1][p][tid]       = tanhf(acc[p][0] + ba);
            act[(L & 1) ^ 1][p][tid + 256] = tanhf(acc[p][1] + bb);
        }
        __syncthreads();
    }

    const int wp = tid >> 5, lane = tid & 31;
    float s = 0.f;
    #pragma unroll
    for (int i = 0; i < 16; i++) {
        int k = lane + 32 * i;
        s = fmaf(act[0][wp][k], W3[k], s);
    }
    #pragma unroll
    for (int off = 16; off; off >>= 1)
        s += __shfl_down_sync(0xffffffffu, s, off);
    if (lane == 0 && p0 + wp < n_bnd)
        g_ub[p0 + wp] = s + b3[0];
}

// ---------------- main GEMM layer (plain fp16 mma.sync, fp32 accum) ----------------
// grid (mtiles, 2). 512 threads = 16 warps (4M x 4N); warp tile M32 x N64.
// 4-stage ring, K-chunk 32. Stage (24KB): A 8KB @+0, B 16KB @+8192.
template<int FINAL>
__global__ void __launch_bounds__(512, 1) layer_k(
    int sIn, const float* __restrict__ bias, const float* __restrict__ W3,
    int n_int)
{
    extern __shared__ float smem[];
    u32 sb = (u32)__cvta_generic_to_shared(smem);
    const int tid = threadIdx.x, lane = tid & 31, w = tid >> 5;
    const int warpM = w & 3, warpN = w >> 2;
    const int mt = blockIdx.x, nhalf = blockIdx.y;

    float* s_bias = smem;          // 256
    float* s_w3   = smem + 256;    // 256
    float* s_red  = smem + 512;    // 128

    if (tid < 256) {
        s_bias[tid] = bias[nhalf * 256 + tid];
        if (FINAL) s_w3[tid] = W3[nhalf * 256 + tid];
    }

    const char* A = (const char*)(gA[sIn] + (size_t)mt * 65536);
    const char* B = (const char*)(gB[sIn] + (size_t)nhalf * 256 * 512);

    auto fill = [&](int kt) {
        u32 base = sb + 4096u + (u32)(kt & 3) * (u32)STAGE_BYTES;
        {
            int ch = tid & 3, row = tid >> 2;
            u32 d = base + (u32)ch * 2048u + (u32)row * 16u;
            cp16(d, A + (size_t)row * 1024 + (size_t)kt * 64 + (size_t)ch * 16);
        }
        #pragma unroll
        for (int i = 0; i < 2; i++) {
            int u = tid + i * 512;
            int ch = u & 3, row = u >> 2;
            u32 d = base + 8192u + (u32)ch * 4096u + (u32)row * 16u;
            cp16(d, B + (size_t)row * 1024 + (size_t)kt * 64 + (size_t)ch * 16);
        }
    };

    float acc[2][8][4];
    #pragma unroll
    for (int mi = 0; mi < 2; mi++)
        #pragma unroll
        for (int ni = 0; ni < 8; ni++)
            #pragma unroll
            for (int r = 0; r < 4; r++) acc[mi][ni][r] = 0.f;

    fill(0); cp_commit();
    fill(1); cp_commit();
    fill(2); cp_commit();

    const int rowA = (lane & 7) + (lane & 8);
    const int chAh = (lane >> 4) & 1;
    const int rowB = (lane & 7) + ((lane & 16) >> 1);
    const int chBh = (lane >> 3) & 1;

    #pragma unroll 1
    for (int kt = 0; kt < 16; kt++) {
        if (kt <= 13) cp_wait2();
        else if (kt == 14) cp_wait1();
        else cp_wait0();
        __syncthreads();
        if (kt + 3 < 16) { fill(kt + 3); cp_commit(); }

        u32 tb = sb + 4096u + (u32)(kt & 3) * (u32)STAGE_BYTES;
        #pragma unroll
        for (int ks = 0; ks < 2; ks++) {
            u32 ah[2][4];
            #pragma unroll
            for (int mi = 0; mi < 2; mi++) {
                int row = warpM * 32 + mi * 16 + rowA;
                u32 ad = tb + (u32)(ks * 2 + chAh) * 2048u + (u32)row * 16u;
                ldsm4(ah[mi][0], ah[mi][1], ah[mi][2], ah[mi][3], ad);
            }
            #pragma unroll
            for (int ni2 = 0; ni2 < 4; ni2++) {
                int row = warpN * 64 + ni2 * 16 + rowB;
                u32 bd = tb + 8192u + (u32)(ks * 2 + chBh) * 4096u + (u32)row * 16u;
                u32 bh[4];
                ldsm4(bh[0], bh[1], bh[2], bh[3], bd);
                #pragma unroll
                for (int mi = 0; mi < 2; mi++) {
                    mma_f16(acc[mi][ni2 * 2],     ah[mi], bh[0], bh[1]);
                    mma_f16(acc[mi][ni2 * 2 + 1], ah[mi], bh[2], bh[3]);
                }
            }
        }
    }
    __syncthreads();   // stage buffers now free for epilogue scratch

    // ---------------- epilogue: quad transpose via per-warp smem scratch ----------------
    // scratch: smem floats [1024 + w*128 .. +128): layout [j][lane]
    const int t4 = lane & 3;
    const int cmy = (lane >> 2) & 3;
    const int bit4 = (lane >> 4) & 1;
    float* scrf = smem + 1024 + w * 128;
    const int rdb = cmy * 32 + bit4 * 16 + t4;   // + m*4
    float dl[4] = {0.f, 0.f, 0.f, 0.f};
    u32* O = (u32*)(gA[sIn ^ 1] + (size_t)mt * 65536);

    #pragma unroll
    for (int mi = 0; mi < 2; mi++) {
        #pragma unroll
        for (int rh = 0; rh < 2; rh++) {
            int Rp = warpM * 32 + mi * 16 + rh * 8 + bit4 * 4;
            #pragma unroll
            for (int nb = 0; nb < 2; nb++) {
                // my assigned column after transpose: ni = nb*4 + cmy
                int ncol = warpN * 64 + (nb * 4 + cmy) * 8 + 2 * t4;
                float o0[4], o1[4];
                #pragma unroll
                for (int ch = 0; ch < 2; ch++) {
                    scrf[lane]      = acc[mi][nb * 4 + 0][rh * 2 + ch];
                    scrf[32 + lane] = acc[mi][nb * 4 + 1][rh * 2 + ch];
                    scrf[64 + lane] = acc[mi][nb * 4 + 2][rh * 2 + ch];
                    scrf[96 + lane] = acc[mi][nb * 4 + 3][rh * 2 + ch];
                    __syncwarp();
                    float zv  = scrf[rdb];
                    float zgx = scrf[rdb + 4];
                    float zgy = scrf[rdb + 8];
                    float zL  = scrf[rdb + 12];
                    __syncwarp();
                    int n_loc = ncol + ch;
                    float tt = tanhf(zv + s_bias[n_loc]);
                    float sd = 1.f - tt * tt;
                    float Lo = fmaf(sd, zL, -2.f * tt * sd * (zgx * zgx + zgy * zgy));
                    if (FINAL) {
                        dl[mi * 2 + rh] = fmaf(Lo, s_w3[n_loc], dl[mi * 2 + rh]);
                    } else {
                        float* o = ch ? o1 : o0;
                        o[0] = tt; o[1] = sd * zgx; o[2] = sd * zgy; o[3] = Lo;
                    }
                }
                if (!FINAL) {
                    u32 colp = (u32)(nhalf * 256 + ncol) >> 1;
                    #pragma unroll
                    for (int m = 0; m < 4; m++)
                        O[(u32)(Rp + m) * 256 + colp] = pack_h2(o0[m], o1[m]);
                }
            }
        }
    }

    if (FINAL) {
        #pragma unroll
        for (int s = 0; s < 4; s++) {
            dl[s] += __shfl_xor_sync(0xffffffffu, dl[s], 1);
            dl[s] += __shfl_xor_sync(0xffffffffu, dl[s], 2);
            dl[s] += __shfl_xor_sync(0xffffffffu, dl[s], 4);
            dl[s] += __shfl_xor_sync(0xffffffffu, dl[s], 8);
        }
        float* s_l = s_red;
        if (lane == 0 || lane == 16) {
            #pragma unroll
            for (int mi = 0; mi < 2; mi++)
                #pragma unroll
                for (int rh = 0; rh < 2; rh++) {
                    int p = warpM * 8 + mi * 4 + rh * 2 + bit4;
                    if (warpN == 0) s_l[p] = dl[mi * 2 + rh];
                }
        }
        __syncthreads();
        for (int q = 1; q < 4; q++) {
            if (warpN == q && (lane == 0 || lane == 16)) {
                #pragma unroll
                for (int mi = 0; mi < 2; mi++)
                    #pragma unroll
                    for (int rh = 0; rh < 2; rh++) {
                        int p = warpM * 8 + mi * 4 + rh * 2 + bit4;
                        s_l[p] += dl[mi * 2 + rh];
                    }
            }
            __syncthreads();
        }
        if (tid < 32) {
            int pt = mt * 32 + tid;
            if (pt < n_int) g_lp[nhalf][pt] = s_l[tid];
        }
    }
}

// ---------------- two-stage deterministic reduction ----------------
__global__ void pinn_partial(const float* __restrict__ xi, int n_int, int n_bnd)
{
    __shared__ double sh[2 * RED_T];
    const int tid = threadIdx.x;
    const int stride = NB_RED * RED_T;
    const float PI = 3.14159265358979f;

    double si = 0.0, sb = 0.0;
    for (int i = blockIdx.x * RED_T + tid; i < n_int; i += stride) {
        float xx = xi[2 * i], yy = xi[2 * i + 1];
        float y2 = yy * yy;
        float sp = sinf(PI * xx);
        float s2, c2; sincosf(PI * y2, &s2, &c2);
        float f = -PI * PI * (1.0f + 4.0f * y2) * sp * s2 + 2.0f * PI * sp * c2;
        float r = (g_lp[0][i] + g_lp[1][i]) - f;
        si += (double)r * r;
    }
    for (int i = blockIdx.x * RED_T + tid; i < n_bnd; i += stride) {
        float u = g_ub[i];
        sb += (double)u * u;
    }
    sh[tid] = si; sh[RED_T + tid] = sb;
    __syncthreads();
    for (int s = RED_T / 2; s > 0; s >>= 1) {
        if (tid < s) { sh[tid] += sh[tid + s]; sh[RED_T + tid] += sh[RED_T + tid + s]; }
        __syncthreads();
    }
    if (tid == 0) {
        g_part[blockIdx.x] = sh[0];
        g_part[NB_RED + blockIdx.x] = sh[RED_T];
    }
}

__global__ void pinn_final(float* __restrict__ out, int n_int, int n_bnd)
{
    __shared__ double sh[2 * NB_RED];
    int tid = threadIdx.x;
    if (tid < 2 * NB_RED) sh[tid] = g_part[tid];
    __syncthreads();
    if (tid == 0) {
        double si = 0.0, sb = 0.0;
        for (int i = 0; i < NB_RED; i++) { si += sh[i]; sb += sh[NB_RED + i]; }
        double il = si / (double)n_int;
        double bl = sb / (double)n_bnd;
        out[0] = (float)((double)ALPHA * il + bl);
        out[1] = (float)il;
        out[2] = (float)bl;
    }
}

extern "C" void kernel_launch(void* const* d_in, const int* in_sizes, int n_in,
                              void* d_out, int out_size)
{
    const float* xi = (const float*)d_in[0];
    const float* xb = (const float*)d_in[1];
    const float* W0 = (const float*)d_in[2];
    const float* b0 = (const float*)d_in[3];
    const float* W1 = (const float*)d_in[4];
    const float* b1 = (const float*)d_in[5];
    const float* W2 = (const float*)d_in[6];
    const float* b2 = (const float*)d_in[7];
    const float* W3 = (const float*)d_in[8];
    const float* b3 = (const float*)d_in[9];

    int n_int = in_sizes[0] / 2;
    int n_bnd = in_sizes[1] / 2;
    int mtiles = (n_int + 31) / 32;
    int bblocks = (n_bnd + BPT - 1) / BPT;

    static int configured = 0;
    if (!configured) {
        cudaFuncSetAttribute(layer_k<0>, cudaFuncAttributeMaxDynamicSharedMemorySize, SMEM_LAYER);
        cudaFuncSetAttribute(layer_k<1>, cudaFuncAttributeMaxDynamicSharedMemorySize, SMEM_LAYER);
        configured = 1;
    }

    prep_all<<<512 + mtiles + bblocks, 256>>>(xi, xb, W0, b0, W1, b1, W2, b2, W3, b3,
                                              n_int, n_bnd, mtiles);
    dim3 grid(mtiles, 2);
    layer_k<0><<<grid, 512, SMEM_LAYER>>>(0, b1, W3, n_int);
    layer_k<1><<<grid, 512, SMEM_LAYER>>>(1, b2, W3, n_int);
    pinn_partial<<<NB_RED, RED_T>>>(xi, n_int, n_bnd);
    pinn_final<<<1, 128>>>((float*)d_out, n_int, n_bnd);
}